// round 2
// baseline (speedup 1.0000x reference)
#include <cuda_runtime.h>
#include <math.h>

#define N_ROWS 4096
#define D_DIM  1024
#define TWO_N  8192
#define INV_TEMP 20.0f
#define SPLIT  16
#define CHUNK  (TWO_N / SPLIT)   // 512 columns per block
#define BM 128
#define BN 128
#define BK 16
#define TM 8
#define TN 8
#define NEG_INF (-1e30f)

// Scratch (no allocations allowed): normalized X, normalized [T;H], diag, partial lse
__device__ float g_Xn[(size_t)N_ROWS * D_DIM];      // 16 MB
__device__ float g_Bn[(size_t)TWO_N * D_DIM];       // 32 MB
__device__ float g_diag[N_ROWS];
__device__ float g_pm[N_ROWS * SPLIT];
__device__ float g_ps[N_ROWS * SPLIT];

// ---------------------------------------------------------------------------
// Kernel 1: row-normalize all three matrices. target -> g_Bn[0:N), neg -> g_Bn[N:2N)
// One block (256 thr) per row; each thread owns one float4 (256*4 = 1024 = D).
// ---------------------------------------------------------------------------
__global__ __launch_bounds__(256) void normalize_kernel(
    const float* __restrict__ inp,
    const float* __restrict__ tgt,
    const float* __restrict__ neg)
{
    int row = blockIdx.x;
    const float* src;
    float* dst;
    if (row < N_ROWS) {
        src = inp + (size_t)row * D_DIM;
        dst = g_Xn + (size_t)row * D_DIM;
    } else if (row < 2 * N_ROWS) {
        int r = row - N_ROWS;
        src = tgt + (size_t)r * D_DIM;
        dst = g_Bn + (size_t)r * D_DIM;
    } else {
        int r = row - 2 * N_ROWS;
        src = neg + (size_t)r * D_DIM;
        dst = g_Bn + (size_t)(N_ROWS + r) * D_DIM;
    }
    int tid = threadIdx.x;
    float4 v = ((const float4*)src)[tid];
    float ss = v.x * v.x + v.y * v.y + v.z * v.z + v.w * v.w;
    #pragma unroll
    for (int o = 16; o; o >>= 1) ss += __shfl_xor_sync(0xffffffffu, ss, o);

    __shared__ float warp_ss[8];
    __shared__ float s_inv;
    int w = tid >> 5, l = tid & 31;
    if (l == 0) warp_ss[w] = ss;
    __syncthreads();
    if (tid == 0) {
        float t = 0.f;
        #pragma unroll
        for (int i = 0; i < 8; i++) t += warp_ss[i];
        s_inv = 1.0f / fmaxf(sqrtf(t), 1e-8f);
    }
    __syncthreads();
    float inv = s_inv;
    v.x *= inv; v.y *= inv; v.z *= inv; v.w *= inv;
    ((float4*)dst)[tid] = v;
}

// ---------------------------------------------------------------------------
// Kernel 2: fused GEMM + online logsumexp.
// Block (bx=chunk, by=row tile): rows [by*128, +128), cols [bx*512, +512).
// 256 threads, 8x8 micro-tile each. Per-thread running (max, sumexp) over its
// 8 rows; combined across the 16 column-threads by warp shuffle at the end.
// Captures pos_sim[i,i] into g_diag and applies the +1 hard-negative weight
// at column N+i.
// ---------------------------------------------------------------------------
__global__ __launch_bounds__(256) void sim_lse_kernel()
{
    __shared__ float As[BK][BM];
    __shared__ float Bs[BK][BN];

    const int chunk = blockIdx.x;
    const int rb    = blockIdx.y;
    const int tid   = threadIdx.x;
    const int tx    = tid & 15;   // column group (8 cols each)
    const int ty    = tid >> 4;   // row group (8 rows each)
    const int row0  = rb * BM;

    float rm[TM], rs[TM];
    #pragma unroll
    for (int i = 0; i < TM; i++) { rm[i] = NEG_INF; rs[i] = 0.f; }

    for (int ct = 0; ct < CHUNK / BN; ct++) {
        const int col0 = chunk * CHUNK + ct * BN;
        float acc[TM][TN];
        #pragma unroll
        for (int i = 0; i < TM; i++)
            #pragma unroll
            for (int j = 0; j < TN; j++) acc[i][j] = 0.f;

        for (int k0 = 0; k0 < D_DIM; k0 += BK) {
            __syncthreads();
            // Load A tile (128x16) and B tile (128x16), transposed into smem.
            // lid: r = lid>>2 (row in tile), c4 = (lid&3)*4 (k offset) -> 64B
            // coalesced per 4 threads.
            #pragma unroll
            for (int lphase = 0; lphase < 2; lphase++) {
                int lid = tid + lphase * 256;
                int r   = lid >> 2;
                int c4  = (lid & 3) * 4;
                float4 a = *(const float4*)&g_Xn[(size_t)(row0 + r) * D_DIM + k0 + c4];
                As[c4 + 0][r] = a.x; As[c4 + 1][r] = a.y;
                As[c4 + 2][r] = a.z; As[c4 + 3][r] = a.w;
                float4 b = *(const float4*)&g_Bn[(size_t)(col0 + r) * D_DIM + k0 + c4];
                Bs[c4 + 0][r] = b.x; Bs[c4 + 1][r] = b.y;
                Bs[c4 + 2][r] = b.z; Bs[c4 + 3][r] = b.w;
            }
            __syncthreads();

            #pragma unroll
            for (int k = 0; k < BK; k++) {
                float a[TM], b[TN];
                #pragma unroll
                for (int i = 0; i < TM; i++) a[i] = As[k][ty * TM + i];
                #pragma unroll
                for (int j = 0; j < TN; j++) b[j] = Bs[k][tx * TN + j];
                #pragma unroll
                for (int i = 0; i < TM; i++)
                    #pragma unroll
                    for (int j = 0; j < TN; j++)
                        acc[i][j] = fmaf(a[i], b[j], acc[i][j]);
            }
        }

        // Epilogue: scale, hard-negative weight, diagonal capture, online LSE.
        #pragma unroll
        for (int i = 0; i < TM; i++) {
            const int gr = row0 + ty * TM + i;
            float v[TN];
            float tmax = NEG_INF;
            #pragma unroll
            for (int j = 0; j < TN; j++) {
                const int gc = col0 + tx * TN + j;
                float x = acc[i][j] * INV_TEMP;
                if (gc == gr) g_diag[gr] = x;          // pos_sim diagonal (once)
                if (gc == N_ROWS + gr) x += 1.0f;      // hard-negative weight
                v[j] = x;
                tmax = fmaxf(tmax, x);
            }
            const float m_new = fmaxf(rm[i], tmax);
            float s = 0.f;
            #pragma unroll
            for (int j = 0; j < TN; j++) s += __expf(v[j] - m_new);
            rs[i] = rs[i] * __expf(rm[i] - m_new) + s;
            rm[i] = m_new;
        }
    }

    // Combine (m, s) across the 16 tx-threads sharing the same rows.
    // tid = ty*16 + tx  => same-ty threads are 16 consecutive lanes of a warp,
    // so xor-shuffles with offsets 8,4,2,1 stay within the group.
    #pragma unroll
    for (int off = 8; off; off >>= 1) {
        #pragma unroll
        for (int i = 0; i < TM; i++) {
            float om = __shfl_xor_sync(0xffffffffu, rm[i], off);
            float os = __shfl_xor_sync(0xffffffffu, rs[i], off);
            float m  = fmaxf(rm[i], om);
            rs[i] = rs[i] * __expf(rm[i] - m) + os * __expf(om - m);
            rm[i] = m;
        }
    }
    if (tx == 0) {
        #pragma unroll
        for (int i = 0; i < TM; i++) {
            int gr = row0 + ty * TM + i;
            g_pm[gr * SPLIT + chunk] = rm[i];
            g_ps[gr * SPLIT + chunk] = rs[i];
        }
    }
}

// ---------------------------------------------------------------------------
// Kernel 3: per-row combine of SPLIT partials -> lse; loss = mean(lse - diag).
// Single block; trivial amount of work.
// ---------------------------------------------------------------------------
__global__ __launch_bounds__(256) void finalize_kernel(float* __restrict__ out)
{
    int tid = threadIdx.x;
    float local = 0.f;
    for (int r = tid; r < N_ROWS; r += 256) {
        float m = NEG_INF;
        #pragma unroll
        for (int c = 0; c < SPLIT; c++) m = fmaxf(m, g_pm[r * SPLIT + c]);
        float s = 0.f;
        #pragma unroll
        for (int c = 0; c < SPLIT; c++)
            s += g_ps[r * SPLIT + c] * __expf(g_pm[r * SPLIT + c] - m);
        float lse = m + logf(s);
        local += lse - g_diag[r];
    }
    #pragma unroll
    for (int o = 16; o; o >>= 1) local += __shfl_xor_sync(0xffffffffu, local, o);
    __shared__ float warp_sum[8];
    int w = tid >> 5, l = tid & 31;
    if (l == 0) warp_sum[w] = local;
    __syncthreads();
    if (tid == 0) {
        float t = 0.f;
        #pragma unroll
        for (int i = 0; i < 8; i++) t += warp_sum[i];
        out[0] = t / (float)N_ROWS;
    }
}

// ---------------------------------------------------------------------------
extern "C" void kernel_launch(void* const* d_in, const int* in_sizes, int n_in,
                              void* d_out, int out_size)
{
    const float* inp = (const float*)d_in[0];
    const float* tgt = (const float*)d_in[1];
    const float* neg = (const float*)d_in[2];
    float* out = (float*)d_out;

    normalize_kernel<<<3 * N_ROWS, 256>>>(inp, tgt, neg);

    dim3 grid(SPLIT, N_ROWS / BM);   // 16 x 32 = 512 blocks
    sim_lse_kernel<<<grid, 256>>>();

    finalize_kernel<<<1, 256>>>(out);
}

// round 4
// speedup vs baseline: 6.2785x; 6.2785x over previous
#include <cuda_runtime.h>
#include <cuda_bf16.h>
#include <math.h>
#include <stdint.h>

#define N_ROWS 4096
#define D_DIM  1024
#define TWO_N  8192
#define INV_TEMP 20.0f
#define NEG_INF (-1e30f)

#define BM 128
#define BN 128
#define BK 32
#define NK (D_DIM / BK)          // 32 k-chunks
#define CT_TILES (TWO_N / BN)    // 64 column tiles
#define RB_TILES (N_ROWS / BM)   // 32 row tiles
#define PCOLS (CT_TILES * 4)     // 256 partials per row (4 warp_n per tile)

// Padded smem row stride: 40 bf16 = 80 bytes. 8 consecutive rows at stride 80
// hit 8 distinct 16B bank-groups mod 128 -> conflict-free ldmatrix & stores.
#define SSTRIDE 40
#define SBUF_BYTES (128 * SSTRIDE * 2)   // 10240 bytes per tile buffer

// -------------------------- scratch (no allocs) ----------------------------
__device__ __nv_bfloat16 g_Xn[(size_t)N_ROWS * D_DIM];   // 8 MB
__device__ __nv_bfloat16 g_Bn[(size_t)TWO_N * D_DIM];    // 16 MB (target ; neg)
__device__ float g_diag[N_ROWS];
__device__ float g_pm[(size_t)N_ROWS * PCOLS];           // 4 MB
__device__ float g_ps[(size_t)N_ROWS * PCOLS];           // 4 MB
__device__ float g_rowloss[N_ROWS];

// -------------------------- PTX helpers ------------------------------------
__device__ __forceinline__ uint32_t smem_u32(const void* p) {
    uint32_t a;
    asm("{ .reg .u64 t; cvta.to.shared.u64 t, %1; cvt.u32.u64 %0, t; }" : "=r"(a) : "l"(p));
    return a;
}

#define CP_ASYNC16(saddr, gptr) \
    asm volatile("cp.async.cg.shared.global [%0], [%1], 16;" :: "r"(saddr), "l"(gptr))
#define CP_COMMIT() asm volatile("cp.async.commit_group;" ::: "memory")
#define CP_WAIT0()  asm volatile("cp.async.wait_group 0;" ::: "memory")

#define LDSM_X4(r, a) \
    asm volatile("ldmatrix.sync.aligned.m8n8.x4.shared.b16 {%0,%1,%2,%3}, [%4];" \
        : "=r"((r)[0]), "=r"((r)[1]), "=r"((r)[2]), "=r"((r)[3]) : "r"(a))
#define LDSM_X2(r, a) \
    asm volatile("ldmatrix.sync.aligned.m8n8.x2.shared.b16 {%0,%1}, [%2];" \
        : "=r"((r)[0]), "=r"((r)[1]) : "r"(a))

#define MMA16816(d, a, b) \
    asm volatile("mma.sync.aligned.m16n8k16.row.col.f32.bf16.bf16.f32 " \
        "{%0,%1,%2,%3}, {%4,%5,%6,%7}, {%8,%9}, {%0,%1,%2,%3};" \
        : "+f"((d)[0]), "+f"((d)[1]), "+f"((d)[2]), "+f"((d)[3]) \
        : "r"((a)[0]), "r"((a)[1]), "r"((a)[2]), "r"((a)[3]), "r"((b)[0]), "r"((b)[1]))

// ---------------------------------------------------------------------------
// Kernel 1: row-normalize -> bf16. target -> g_Bn[0:N), hard_neg -> g_Bn[N:2N)
// ---------------------------------------------------------------------------
__global__ __launch_bounds__(256) void normalize_kernel(
    const float* __restrict__ inp,
    const float* __restrict__ tgt,
    const float* __restrict__ neg)
{
    int row = blockIdx.x;
    const float* src;
    __nv_bfloat16* dst;
    if (row < N_ROWS) {
        src = inp + (size_t)row * D_DIM;
        dst = g_Xn + (size_t)row * D_DIM;
    } else if (row < 2 * N_ROWS) {
        int r = row - N_ROWS;
        src = tgt + (size_t)r * D_DIM;
        dst = g_Bn + (size_t)r * D_DIM;
    } else {
        int r = row - 2 * N_ROWS;
        src = neg + (size_t)r * D_DIM;
        dst = g_Bn + (size_t)(N_ROWS + r) * D_DIM;
    }
    int tid = threadIdx.x;
    float4 v = ((const float4*)src)[tid];
    float ss = v.x * v.x + v.y * v.y + v.z * v.z + v.w * v.w;
    #pragma unroll
    for (int o = 16; o; o >>= 1) ss += __shfl_xor_sync(0xffffffffu, ss, o);

    __shared__ float warp_ss[8];
    __shared__ float s_inv;
    int w = tid >> 5, l = tid & 31;
    if (l == 0) warp_ss[w] = ss;
    __syncthreads();
    if (tid == 0) {
        float t = 0.f;
        #pragma unroll
        for (int i = 0; i < 8; i++) t += warp_ss[i];
        s_inv = 1.0f / fmaxf(sqrtf(t), 1e-8f);
    }
    __syncthreads();
    float inv = s_inv;
    __nv_bfloat162 h0 = __floats2bfloat162_rn(v.x * inv, v.y * inv);
    __nv_bfloat162 h1 = __floats2bfloat162_rn(v.z * inv, v.w * inv);
    uint2 packed;
    packed.x = *(uint32_t*)&h0;
    packed.y = *(uint32_t*)&h1;
    ((uint2*)dst)[tid] = packed;
}

// ---------------------------------------------------------------------------
// Kernel 2: bf16 HMMA GEMM (mma.sync m16n8k16) + fused online logsumexp.
// Block (ct, rb): 128x128 logits tile. 8 warps as 2x4 (warp tile 64x32).
// cp.async double-buffered K loop, 80B-padded conflict-free smem.
// Epilogue: x20 scale, diag capture, +1 hard-negative weight, quad-reduced
// per-row (m, s) partials -> g_pm/g_ps[row][ct*4 + warp_n].
// ---------------------------------------------------------------------------
__global__ __launch_bounds__(256) void sim_lse_mma()
{
    __shared__ alignas(1024) __nv_bfloat16 sA[2][128 * SSTRIDE];
    __shared__ alignas(1024) __nv_bfloat16 sB[2][128 * SSTRIDE];

    const int tid    = threadIdx.x;
    const int wid    = tid >> 5;
    const int lane   = tid & 31;
    const int warp_m = wid >> 2;        // 0..1
    const int warp_n = wid & 3;         // 0..3
    const int ct     = blockIdx.x;      // 0..63
    const int rb     = blockIdx.y;      // 0..31
    const int row0   = rb * BM;
    const int col0   = ct * BN;

    const uint32_t aA = smem_u32(sA);
    const uint32_t aB = smem_u32(sB);

    // cp.async source/dest for this thread (2 segments per matrix per chunk)
    const int ldr0 = tid >> 2;                 // row for phase 0 (idx = tid)
    const int ldc0 = tid & 3;                  // 16B chunk (8 bf16) in row
    const int ldr1 = (tid + 256) >> 2;
    const int ldc1 = (tid + 256) & 3;

    float acc[4][4][4];
    #pragma unroll
    for (int mt = 0; mt < 4; mt++)
        #pragma unroll
        for (int nt = 0; nt < 4; nt++)
            #pragma unroll
            for (int q = 0; q < 4; q++) acc[mt][nt][q] = 0.f;

    // ldmatrix lane addresses (byte offsets within a buffer)
    const uint32_t a_lm = (uint32_t)((warp_m * 64 + (lane & 15)) * (SSTRIDE * 2)
                                     + (lane >> 4) * 16);
    const uint32_t b_lm = (uint32_t)((warp_n * 32 + (lane & 7)) * (SSTRIDE * 2)
                                     + ((lane >> 3) & 1) * 16);

    // prologue: chunk 0 -> buf 0
    {
        const int k0 = 0;
        CP_ASYNC16(aA + ldr0 * (SSTRIDE * 2) + ldc0 * 16,
                   &g_Xn[(size_t)(row0 + ldr0) * D_DIM + k0 + ldc0 * 8]);
        CP_ASYNC16(aB + ldr0 * (SSTRIDE * 2) + ldc0 * 16,
                   &g_Bn[(size_t)(col0 + ldr0) * D_DIM + k0 + ldc0 * 8]);
        CP_ASYNC16(aA + ldr1 * (SSTRIDE * 2) + ldc1 * 16,
                   &g_Xn[(size_t)(row0 + ldr1) * D_DIM + k0 + ldc1 * 8]);
        CP_ASYNC16(aB + ldr1 * (SSTRIDE * 2) + ldc1 * 16,
                   &g_Bn[(size_t)(col0 + ldr1) * D_DIM + k0 + ldc1 * 8]);
        CP_COMMIT();
    }

    int buf = 0;
    for (int kc = 0; kc < NK; kc++) {
        CP_WAIT0();
        __syncthreads();

        if (kc + 1 < NK) {
            const int k0 = (kc + 1) * BK;
            const uint32_t dA = aA + (buf ^ 1) * SBUF_BYTES;
            const uint32_t dB = aB + (buf ^ 1) * SBUF_BYTES;
            CP_ASYNC16(dA + ldr0 * (SSTRIDE * 2) + ldc0 * 16,
                       &g_Xn[(size_t)(row0 + ldr0) * D_DIM + k0 + ldc0 * 8]);
            CP_ASYNC16(dB + ldr0 * (SSTRIDE * 2) + ldc0 * 16,
                       &g_Bn[(size_t)(col0 + ldr0) * D_DIM + k0 + ldc0 * 8]);
            CP_ASYNC16(dA + ldr1 * (SSTRIDE * 2) + ldc1 * 16,
                       &g_Xn[(size_t)(row0 + ldr1) * D_DIM + k0 + ldc1 * 8]);
            CP_ASYNC16(dB + ldr1 * (SSTRIDE * 2) + ldc1 * 16,
                       &g_Bn[(size_t)(col0 + ldr1) * D_DIM + k0 + ldc1 * 8]);
            CP_COMMIT();
        }

        const uint32_t baseA = aA + buf * SBUF_BYTES;
        const uint32_t baseB = aB + buf * SBUF_BYTES;
        #pragma unroll
        for (int ks = 0; ks < 2; ks++) {
            uint32_t af[4][4], bf[4][2];
            #pragma unroll
            for (int mt = 0; mt < 4; mt++)
                LDSM_X4(af[mt], baseA + a_lm + ks * 32 + mt * 16 * (SSTRIDE * 2));
            #pragma unroll
            for (int nt = 0; nt < 4; nt++)
                LDSM_X2(bf[nt], baseB + b_lm + ks * 32 + nt * 8 * (SSTRIDE * 2));
            #pragma unroll
            for (int mt = 0; mt < 4; mt++)
                #pragma unroll
                for (int nt = 0; nt < 4; nt++)
                    MMA16816(acc[mt][nt], af[mt], bf[nt]);
        }
        buf ^= 1;
    }

    // ---- Epilogue: per-row online LSE over this warp's 32 columns ----
    // acc regs {0,1}: row = lane/4,     cols 2*(lane%4)+{0,1}
    //          {2,3}: row = lane/4 + 8, cols same
    #pragma unroll
    for (int mt = 0; mt < 4; mt++) {
        #pragma unroll
        for (int h = 0; h < 2; h++) {
            const int gr = row0 + warp_m * 64 + mt * 16 + (lane >> 2) + h * 8;
            float v[8];
            float m = NEG_INF;
            #pragma unroll
            for (int nt = 0; nt < 4; nt++) {
                #pragma unroll
                for (int j = 0; j < 2; j++) {
                    float x = acc[mt][nt][h * 2 + j] * INV_TEMP;
                    const int gc = col0 + warp_n * 32 + nt * 8 + (lane & 3) * 2 + j;
                    if (gc == gr) g_diag[gr] = x;           // pos_sim diagonal
                    if (gc == N_ROWS + gr) x += 1.0f;       // hard-negative weight
                    v[nt * 2 + j] = x;
                    m = fmaxf(m, x);
                }
            }
            float s = 0.f;
            #pragma unroll
            for (int j = 0; j < 8; j++) s += __expf(v[j] - m);
            // combine across the 4 lanes of the quad (same row, different cols)
            #pragma unroll
            for (int off = 1; off <= 2; off <<= 1) {
                float om = __shfl_xor_sync(0xffffffffu, m, off);
                float os = __shfl_xor_sync(0xffffffffu, s, off);
                float mn = fmaxf(m, om);
                s = s * __expf(m - mn) + os * __expf(om - mn);
                m = mn;
            }
            if ((lane & 3) == 0) {
                const size_t p = (size_t)gr * PCOLS + ct * 4 + warp_n;
                g_pm[p] = m;
                g_ps[p] = s;
            }
        }
    }
}

// ---------------------------------------------------------------------------
// Kernel 3a: per-row combine of 256 partials -> lse - diag
// ---------------------------------------------------------------------------
__global__ __launch_bounds__(256) void rowloss_kernel()
{
    int r = blockIdx.x * 256 + threadIdx.x;
    const float* pm = &g_pm[(size_t)r * PCOLS];
    const float* ps = &g_ps[(size_t)r * PCOLS];
    float m = NEG_INF;
    #pragma unroll 8
    for (int c = 0; c < PCOLS; c++) m = fmaxf(m, pm[c]);
    float s = 0.f;
    #pragma unroll 8
    for (int c = 0; c < PCOLS; c++) s += ps[c] * __expf(pm[c] - m);
    g_rowloss[r] = (m + logf(s)) - g_diag[r];
}

// ---------------------------------------------------------------------------
// Kernel 3b: deterministic single-block mean over 4096 rows.
// ---------------------------------------------------------------------------
__global__ __launch_bounds__(256) void finalize_kernel(float* __restrict__ out)
{
    int tid = threadIdx.x;
    float local = 0.f;
    for (int r = tid; r < N_ROWS; r += 256) local += g_rowloss[r];
    #pragma unroll
    for (int o = 16; o; o >>= 1) local += __shfl_xor_sync(0xffffffffu, local, o);
    __shared__ float warp_sum[8];
    int w = tid >> 5, l = tid & 31;
    if (l == 0) warp_sum[w] = local;
    __syncthreads();
    if (tid == 0) {
        float t = 0.f;
        #pragma unroll
        for (int i = 0; i < 8; i++) t += warp_sum[i];
        out[0] = t / (float)N_ROWS;
    }
}

// ---------------------------------------------------------------------------
extern "C" void kernel_launch(void* const* d_in, const int* in_sizes, int n_in,
                              void* d_out, int out_size)
{
    const float* inp = (const float*)d_in[0];
    const float* tgt = (const float*)d_in[1];
    const float* neg = (const float*)d_in[2];
    float* out = (float*)d_out;

    normalize_kernel<<<3 * N_ROWS, 256>>>(inp, tgt, neg);

    dim3 grid(CT_TILES, RB_TILES);   // 64 x 32 = 2048 CTAs
    sim_lse_mma<<<grid, 256>>>();

    rowloss_kernel<<<N_ROWS / 256, 256>>>();
    finalize_kernel<<<1, 256>>>(out);
}

// round 5
// speedup vs baseline: 6.6403x; 1.0576x over previous
#include <cuda_runtime.h>
#include <cuda_bf16.h>
#include <math.h>
#include <stdint.h>

#define N_ROWS 4096
#define D_DIM  1024
#define TWO_N  8192
#define INV_TEMP 20.0f
#define NEG_INF (-1e30f)

#define BM 128
#define BN 128
#define BK 32
#define NK (D_DIM / BK)          // 32 k-chunks
#define CT_TILES (TWO_N / BN)    // 64 column tiles
#define RB_TILES (N_ROWS / BM)   // 32 row tiles
#define PCOLS (CT_TILES * 4)     // 256 partials per row (4 warp_n per tile)
#define NSTAGE 3
#define SBUF_BYTES (128 * 64)    // 8 KB: 128 rows x 64B (32 bf16), XOR swizzled

// XOR swizzle: row r (0..127), 16B chunk c (0..3) -> byte offset.
// chunk' = c ^ ((r>>1)&3). Conflict-free for cp.async 16B stores and all
// ldmatrix phases (8 consecutive rows hit 8 distinct 16B bank groups mod 128B).
#define SWOFF(r, c) (((uint32_t)(r) << 6) | ((((c) ^ (((r) >> 1) & 3))) << 4))

// -------------------------- scratch (no allocs) ----------------------------
__device__ __nv_bfloat16 g_Xn[(size_t)N_ROWS * D_DIM];   // 8 MB
__device__ __nv_bfloat16 g_Bn[(size_t)TWO_N * D_DIM];    // 16 MB (target ; neg)
__device__ float g_diag[N_ROWS];
__device__ float g_pm[(size_t)N_ROWS * PCOLS];           // 4 MB
__device__ float g_ps[(size_t)N_ROWS * PCOLS];           // 4 MB
__device__ float g_bsum[16];

// -------------------------- PTX helpers ------------------------------------
__device__ __forceinline__ uint32_t smem_u32(const void* p) {
    uint32_t a;
    asm("{ .reg .u64 t; cvta.to.shared.u64 t, %1; cvt.u32.u64 %0, t; }" : "=r"(a) : "l"(p));
    return a;
}

#define CP_ASYNC16(saddr, gptr) \
    asm volatile("cp.async.cg.shared.global [%0], [%1], 16;" :: "r"(saddr), "l"(gptr))
#define CP_COMMIT() asm volatile("cp.async.commit_group;" ::: "memory")
#define CP_WAIT1()  asm volatile("cp.async.wait_group 1;" ::: "memory")

#define LDSM_X4(r, a) \
    asm volatile("ldmatrix.sync.aligned.m8n8.x4.shared.b16 {%0,%1,%2,%3}, [%4];" \
        : "=r"((r)[0]), "=r"((r)[1]), "=r"((r)[2]), "=r"((r)[3]) : "r"(a))
#define LDSM_X2(r, a) \
    asm volatile("ldmatrix.sync.aligned.m8n8.x2.shared.b16 {%0,%1}, [%2];" \
        : "=r"((r)[0]), "=r"((r)[1]) : "r"(a))

#define MMA16816(d, a, b) \
    asm volatile("mma.sync.aligned.m16n8k16.row.col.f32.bf16.bf16.f32 " \
        "{%0,%1,%2,%3}, {%4,%5,%6,%7}, {%8,%9}, {%0,%1,%2,%3};" \
        : "+f"((d)[0]), "+f"((d)[1]), "+f"((d)[2]), "+f"((d)[3]) \
        : "r"((a)[0]), "r"((a)[1]), "r"((a)[2]), "r"((a)[3]), "r"((b)[0]), "r"((b)[1]))

// ---------------------------------------------------------------------------
// Kernel 1: row-normalize -> bf16, warp-per-row (no block sync).
// target -> g_Bn[0:N), hard_neg -> g_Bn[N:2N)
// ---------------------------------------------------------------------------
__global__ __launch_bounds__(256) void normalize_kernel(
    const float* __restrict__ inp,
    const float* __restrict__ tgt,
    const float* __restrict__ neg)
{
    const int wid  = threadIdx.x >> 5;
    const int lane = threadIdx.x & 31;
    const int row  = blockIdx.x * 8 + wid;     // 0..12287

    const float* src;
    __nv_bfloat16* dst;
    if (row < N_ROWS) {
        src = inp + (size_t)row * D_DIM;
        dst = g_Xn + (size_t)row * D_DIM;
    } else if (row < 2 * N_ROWS) {
        int r = row - N_ROWS;
        src = tgt + (size_t)r * D_DIM;
        dst = g_Bn + (size_t)r * D_DIM;
    } else {
        int r = row - 2 * N_ROWS;
        src = neg + (size_t)r * D_DIM;
        dst = g_Bn + (size_t)(N_ROWS + r) * D_DIM;
    }

    float4 v[8];
    float ss = 0.f;
    #pragma unroll
    for (int i = 0; i < 8; i++) {
        v[i] = ((const float4*)src)[lane + 32 * i];
        ss += v[i].x * v[i].x + v[i].y * v[i].y + v[i].z * v[i].z + v[i].w * v[i].w;
    }
    #pragma unroll
    for (int o = 16; o; o >>= 1) ss += __shfl_xor_sync(0xffffffffu, ss, o);
    const float inv = 1.0f / fmaxf(sqrtf(ss), 1e-8f);

    #pragma unroll
    for (int i = 0; i < 8; i++) {
        __nv_bfloat162 h0 = __floats2bfloat162_rn(v[i].x * inv, v[i].y * inv);
        __nv_bfloat162 h1 = __floats2bfloat162_rn(v[i].z * inv, v[i].w * inv);
        uint2 packed;
        packed.x = *(uint32_t*)&h0;
        packed.y = *(uint32_t*)&h1;
        ((uint2*)dst)[lane + 32 * i] = packed;
    }
}

// ---------------------------------------------------------------------------
// Kernel 2: bf16 HMMA GEMM (mma.sync m16n8k16) + fused online logsumexp.
// 128x128 tile per CTA, 8 warps (2x4), 3-stage cp.async pipeline,
// XOR-swizzled 64B-row smem (48 KB total, conflict-free).
// ---------------------------------------------------------------------------
__global__ __launch_bounds__(256) void sim_lse_mma()
{
    __shared__ alignas(1024) __nv_bfloat16 sA[NSTAGE][128 * 32];
    __shared__ alignas(1024) __nv_bfloat16 sB[NSTAGE][128 * 32];

    const int tid    = threadIdx.x;
    const int wid    = tid >> 5;
    const int lane   = tid & 31;
    const int warp_m = wid >> 2;        // 0..1
    const int warp_n = wid & 3;         // 0..3
    const int ct     = blockIdx.x;      // 0..63
    const int rb     = blockIdx.y;      // 0..31
    const int row0   = rb * BM;
    const int col0   = ct * BN;

    const uint32_t aA = smem_u32(sA);
    const uint32_t aB = smem_u32(sB);

    // cp.async: thread handles segments tid and tid+256 (row = seg>>2, chunk = seg&3)
    const int ldr0 = tid >> 2;
    const int ldc0 = tid & 3;
    const int ldr1 = (tid + 256) >> 2;
    const int ldc1 = (tid + 256) & 3;
    const uint32_t d0 = SWOFF(ldr0, ldc0);
    const uint32_t d1 = SWOFF(ldr1, ldc1);
    const __nv_bfloat16* gA0 = &g_Xn[(size_t)(row0 + ldr0) * D_DIM + ldc0 * 8];
    const __nv_bfloat16* gA1 = &g_Xn[(size_t)(row0 + ldr1) * D_DIM + ldc1 * 8];
    const __nv_bfloat16* gB0 = &g_Bn[(size_t)(col0 + ldr0) * D_DIM + ldc0 * 8];
    const __nv_bfloat16* gB1 = &g_Bn[(size_t)(col0 + ldr1) * D_DIM + ldc1 * 8];

    // Precomputed ldmatrix lane offsets (within one stage buffer)
    uint32_t a_off[4][2], b_off[4][2];
    #pragma unroll
    for (int mt = 0; mt < 4; mt++) {
        const int r = warp_m * 64 + mt * 16 + (lane & 15);
        const int cb = lane >> 4;
        #pragma unroll
        for (int ks = 0; ks < 2; ks++) a_off[mt][ks] = SWOFF(r, ks * 2 + cb);
    }
    #pragma unroll
    for (int nt = 0; nt < 4; nt++) {
        const int r = warp_n * 32 + nt * 8 + (lane & 7);
        const int cb = (lane >> 3) & 1;
        #pragma unroll
        for (int ks = 0; ks < 2; ks++) b_off[nt][ks] = SWOFF(r, ks * 2 + cb);
    }

    float acc[4][4][4];
    #pragma unroll
    for (int mt = 0; mt < 4; mt++)
        #pragma unroll
        for (int nt = 0; nt < 4; nt++)
            #pragma unroll
            for (int q = 0; q < 4; q++) acc[mt][nt][q] = 0.f;

    // prologue: stages 0 and 1
    #pragma unroll
    for (int p = 0; p < 2; p++) {
        const int k0 = p * BK;
        const uint32_t dA = aA + p * SBUF_BYTES;
        const uint32_t dB = aB + p * SBUF_BYTES;
        CP_ASYNC16(dA + d0, gA0 + k0);
        CP_ASYNC16(dB + d0, gB0 + k0);
        CP_ASYNC16(dA + d1, gA1 + k0);
        CP_ASYNC16(dB + d1, gB1 + k0);
        CP_COMMIT();
    }

    int stage = 0;
    for (int kc = 0; kc < NK; kc++) {
        CP_WAIT1();
        __syncthreads();

        // prefetch kc+2 into stage (kc+2)%3 (that buffer finished compute in kc-1)
        if (kc + 2 < NK) {
            const int ps = (stage + 2 >= NSTAGE) ? stage + 2 - NSTAGE : stage + 2;
            const int k0 = (kc + 2) * BK;
            const uint32_t dA = aA + ps * SBUF_BYTES;
            const uint32_t dB = aB + ps * SBUF_BYTES;
            CP_ASYNC16(dA + d0, gA0 + k0);
            CP_ASYNC16(dB + d0, gB0 + k0);
            CP_ASYNC16(dA + d1, gA1 + k0);
            CP_ASYNC16(dB + d1, gB1 + k0);
        }
        CP_COMMIT();

        const uint32_t baseA = aA + stage * SBUF_BYTES;
        const uint32_t baseB = aB + stage * SBUF_BYTES;
        #pragma unroll
        for (int ks = 0; ks < 2; ks++) {
            uint32_t af[4][4], bf[4][2];
            #pragma unroll
            for (int mt = 0; mt < 4; mt++) LDSM_X4(af[mt], baseA + a_off[mt][ks]);
            #pragma unroll
            for (int nt = 0; nt < 4; nt++) LDSM_X2(bf[nt], baseB + b_off[nt][ks]);
            #pragma unroll
            for (int mt = 0; mt < 4; mt++)
                #pragma unroll
                for (int nt = 0; nt < 4; nt++)
                    MMA16816(acc[mt][nt], af[mt], bf[nt]);
        }
        stage = (stage + 1 >= NSTAGE) ? 0 : stage + 1;
    }

    // ---- Epilogue: per-row online LSE over this warp's 32 columns ----
    #pragma unroll
    for (int mt = 0; mt < 4; mt++) {
        #pragma unroll
        for (int h = 0; h < 2; h++) {
            const int gr = row0 + warp_m * 64 + mt * 16 + (lane >> 2) + h * 8;
            float v[8];
            float m = NEG_INF;
            #pragma unroll
            for (int nt = 0; nt < 4; nt++) {
                #pragma unroll
                for (int j = 0; j < 2; j++) {
                    float x = acc[mt][nt][h * 2 + j] * INV_TEMP;
                    const int gc = col0 + warp_n * 32 + nt * 8 + (lane & 3) * 2 + j;
                    if (gc == gr) g_diag[gr] = x;           // pos_sim diagonal
                    if (gc == N_ROWS + gr) x += 1.0f;       // hard-negative weight
                    v[nt * 2 + j] = x;
                    m = fmaxf(m, x);
                }
            }
            float s = 0.f;
            #pragma unroll
            for (int j = 0; j < 8; j++) s += __expf(v[j] - m);
            #pragma unroll
            for (int off = 1; off <= 2; off <<= 1) {
                float om = __shfl_xor_sync(0xffffffffu, m, off);
                float os = __shfl_xor_sync(0xffffffffu, s, off);
                float mn = fmaxf(m, om);
                s = s * __expf(m - mn) + os * __expf(om - mn);
                m = mn;
            }
            if ((lane & 3) == 0) {
                const size_t p = (size_t)gr * PCOLS + ct * 4 + warp_n;
                g_pm[p] = m;
                g_ps[p] = s;
            }
        }
    }
}

// ---------------------------------------------------------------------------
// Kernel 3a: per-row combine (256 partials) -> lse - diag; block partial sum.
// ---------------------------------------------------------------------------
__global__ __launch_bounds__(256) void rowloss_kernel()
{
    const int tid = threadIdx.x;
    const int r = blockIdx.x * 256 + tid;
    const float* pm = &g_pm[(size_t)r * PCOLS];
    const float* ps = &g_ps[(size_t)r * PCOLS];
    float m = NEG_INF;
    #pragma unroll 8
    for (int c = 0; c < PCOLS; c++) m = fmaxf(m, pm[c]);
    float s = 0.f;
    #pragma unroll 8
    for (int c = 0; c < PCOLS; c++) s += ps[c] * __expf(pm[c] - m);
    float local = (m + logf(s)) - g_diag[r];

    #pragma unroll
    for (int o = 16; o; o >>= 1) local += __shfl_xor_sync(0xffffffffu, local, o);
    __shared__ float warp_sum[8];
    const int w = tid >> 5, l = tid & 31;
    if (l == 0) warp_sum[w] = local;
    __syncthreads();
    if (tid == 0) {
        float t = 0.f;
        #pragma unroll
        for (int i = 0; i < 8; i++) t += warp_sum[i];
        g_bsum[blockIdx.x] = t;
    }
}

// ---------------------------------------------------------------------------
// Kernel 3b: one warp sums the 16 block partials.
// ---------------------------------------------------------------------------
__global__ __launch_bounds__(32) void finalize_kernel(float* __restrict__ out)
{
    const int lane = threadIdx.x;
    float v = (lane < 16) ? g_bsum[lane] : 0.f;
    #pragma unroll
    for (int o = 16; o; o >>= 1) v += __shfl_xor_sync(0xffffffffu, v, o);
    if (lane == 0) out[0] = v / (float)N_ROWS;
}

// ---------------------------------------------------------------------------
extern "C" void kernel_launch(void* const* d_in, const int* in_sizes, int n_in,
                              void* d_out, int out_size)
{
    const float* inp = (const float*)d_in[0];
    const float* tgt = (const float*)d_in[1];
    const float* neg = (const float*)d_in[2];
    float* out = (float*)d_out;

    normalize_kernel<<<(3 * N_ROWS) / 8, 256>>>(inp, tgt, neg);

    dim3 grid(CT_TILES, RB_TILES);   // 64 x 32 = 2048 CTAs
    sim_lse_mma<<<grid, 256>>>();

    rowloss_kernel<<<N_ROWS / 256, 256>>>();
    finalize_kernel<<<1, 32>>>(out);
}